// round 8
// baseline (speedup 1.0000x reference)
#include <cuda_runtime.h>
#include <cstdint>

// Problem constants (match reference_code)
#define VOC_SIZE 1000000
#define EMBED_DIM 64
#define N_UPD 262144
#define N_Q (4096 * 200)  // 819200 query rows

// Scratch (allocation-free __device__ globals).
// g_count: per-row update multiplicity, fully re-zeroed every replay (M0).
// g_src:   for count==1 rows, index of the unique update (single writer).
// g_work:  compacted list of updates whose row has count>1 (worklist),
//          g_ndup entries, rebuilt every replay.
// g_delta: accumulator used ONLY for dup rows: zeroed (K2b) then atomically
//          accumulated (K2c) each replay -> deterministic.
__device__ float g_delta[(size_t)VOC_SIZE * EMBED_DIM];   // 256 MB
__device__ int   g_count[1 << 20];                        // 4 MB (padded)
__device__ int   g_src[1 << 20];                          // 4 MB
__device__ int   g_work[N_UPD];                           // 1 MB (worst case)
__device__ int   g_ndup;

typedef unsigned long long u64;

// 32-byte table load with L2 evict_last (sm_103a: modifier requires
// .v8.b32 / .v4.b64 width). Duplicate queries re-read table rows; bias them
// to stay resident in L2.
__device__ __forceinline__ void ldg_evict_last_32B(const float* p,
                                                   u64& x, u64& y, u64& z, u64& w) {
    asm("ld.global.nc.L2::evict_last.v4.b64 {%0,%1,%2,%3}, [%4];"
        : "=l"(x), "=l"(y), "=l"(z), "=l"(w) : "l"(p));
}

__device__ __forceinline__ void ldg_32B(const float* p,
                                        u64& x, u64& y, u64& z, u64& w) {
    asm("ld.global.nc.v4.b64 {%0,%1,%2,%3}, [%4];"
        : "=l"(x), "=l"(y), "=l"(z), "=l"(w) : "l"(p));
}

// Streaming store (evict-first): output is written once and never re-read.
__device__ __forceinline__ void stg_cs_32B(float* p, u64 x, u64 y, u64 z, u64 w) {
    asm volatile("st.global.cs.v4.b64 [%0], {%1,%2,%3,%4};"
                 :: "l"(p), "l"(x), "l"(y), "l"(z), "l"(w) : "memory");
}

__device__ __forceinline__ u64 pack2(float lo, float hi) {
    return ((u64)__float_as_uint(hi) << 32) | (u64)__float_as_uint(lo);
}
__device__ __forceinline__ float f_lo(u64 v) { return __uint_as_float((unsigned)v); }
__device__ __forceinline__ float f_hi(u64 v) { return __uint_as_float((unsigned)(v >> 32)); }

// M0: zero the count array (4 MB) + dup counter.
__global__ void zero_count_kernel() {
    int t = blockIdx.x * blockDim.x + threadIdx.x;
    u64 z = 0ULL;
    asm volatile("st.global.v4.b64 [%0], {%1,%1,%1,%1};"
                 :: "l"(&g_count[t * 8]), "l"(z) : "memory");
    if (t == 0) g_ndup = 0;
}

// K2a: per-row multiplicity + source index. Two independent updates per
// thread for MLP. g_src races on dup rows only, where it's never read.
__global__ void count_kernel(const int* __restrict__ indices) {
    int t = blockIdx.x * blockDim.x + threadIdx.x;   // 0 .. N_UPD/2-1
    int i1 = t + N_UPD / 2;
    int r0 = indices[t];
    int r1 = indices[i1];
    atomicAdd(&g_count[r0], 1);
    atomicAdd(&g_count[r1], 1);
    g_src[r0] = t;
    g_src[r1] = i1;
}

// K2w: compact the dup updates (~13%) into a worklist so the zero/scatter
// kernels only touch real work instead of predicating 2M threads.
__global__ void build_worklist_kernel(const int* __restrict__ indices) {
    int i = blockIdx.x * blockDim.x + threadIdx.x;   // 0 .. N_UPD-1
    int row = indices[i];
    if (g_count[row] > 1) {
        int slot = atomicAdd(&g_ndup, 1);
        g_work[slot] = i;
    }
}

#define WORK_THREADS (512 * 256)   // fixed grid; strides over 8*g_ndup tasks

// K2b: zero delta rows on the worklist (redundant zeroing by duplicate
// entries of the same row is harmless). 8 lanes x 32B per entry.
__global__ void zero_dup_kernel(const int* __restrict__ indices) {
    int n8 = g_ndup * 8;
    u64 z = 0ULL;
    for (int t = blockIdx.x * blockDim.x + threadIdx.x; t < n8; t += WORK_THREADS) {
        int e = t >> 3;
        int j = t & 7;
        int row = indices[g_work[e]];
        float* p = &g_delta[(size_t)row * EMBED_DIM + j * 8];
        asm volatile("st.global.v4.b64 [%0], {%1,%1,%1,%1};"
                     :: "l"(p), "l"(z) : "memory");
    }
}

// K2c: accumulate worklist updates into delta via vector reduction atomics.
__global__ void scatter_dup_kernel(const int* __restrict__ indices,
                                   const float* __restrict__ upd) {
    int n8 = g_ndup * 8;
    for (int t = blockIdx.x * blockDim.x + threadIdx.x; t < n8; t += WORK_THREADS) {
        int e = t >> 3;
        int j = t & 7;
        int i = g_work[e];
        int row = indices[i];
        u64 x, y, z, w;
        ldg_32B(&upd[(size_t)i * EMBED_DIM + j * 8], x, y, z, w);
        float* p = &g_delta[(size_t)row * EMBED_DIM + j * 8];
        asm volatile("red.global.add.v4.f32 [%0], {%1,%2,%3,%4};"
                     :: "l"(p), "f"(f_lo(x)), "f"(f_hi(x)), "f"(f_lo(y)), "f"(f_hi(y))
                     : "memory");
        asm volatile("red.global.add.v4.f32 [%0], {%1,%2,%3,%4};"
                     :: "l"(p + 4), "f"(f_lo(z)), "f"(f_hi(z)), "f"(f_lo(w)), "f"(f_hi(w))
                     : "memory");
    }
}

// K3: gather. out[i] = table[q] + (count==0 ? 0 : count==1 ? upd[src[q]]
//                                                           : delta[q]).
// 8 threads per 256B row, 32B per thread; each thread handles two query rows
// (i, i+N_Q/2) for MLP. Table reads: L2 evict_last. Output: streaming stores.
__global__ void gather_kernel(const float* __restrict__ table,
                              const int* __restrict__ qs,
                              const float* __restrict__ upd,
                              float* __restrict__ out) {
    int t = blockIdx.x * blockDim.x + threadIdx.x;   // 0 .. N_Q*4-1
    int i0 = t >> 3;
    int j  = t & 7;
    int i1 = i0 + (N_Q / 2);

    int r0 = qs[i0];
    int r1 = qs[i1];
    size_t o0 = (size_t)r0 * EMBED_DIM + j * 8;
    size_t o1 = (size_t)r1 * EMBED_DIM + j * 8;

    u64 x0, y0, z0, w0, x1, y1, z1, w1;
    ldg_evict_last_32B(&table[o0], x0, y0, z0, w0);
    ldg_evict_last_32B(&table[o1], x1, y1, z1, w1);
    int c0 = g_count[r0];
    int c1 = g_count[r1];

    if (c0) {
        const float* dp = (c0 == 1)
            ? &upd[(size_t)g_src[r0] * EMBED_DIM + j * 8]
            : &g_delta[o0];
        float4 da = __ldg(reinterpret_cast<const float4*>(dp));
        float4 db = __ldg(reinterpret_cast<const float4*>(dp + 4));
        x0 = pack2(f_lo(x0) + da.x, f_hi(x0) + da.y);
        y0 = pack2(f_lo(y0) + da.z, f_hi(y0) + da.w);
        z0 = pack2(f_lo(z0) + db.x, f_hi(z0) + db.y);
        w0 = pack2(f_lo(w0) + db.z, f_hi(w0) + db.w);
    }
    if (c1) {
        const float* dp = (c1 == 1)
            ? &upd[(size_t)g_src[r1] * EMBED_DIM + j * 8]
            : &g_delta[o1];
        float4 da = __ldg(reinterpret_cast<const float4*>(dp));
        float4 db = __ldg(reinterpret_cast<const float4*>(dp + 4));
        x1 = pack2(f_lo(x1) + da.x, f_hi(x1) + da.y);
        y1 = pack2(f_lo(y1) + da.z, f_hi(y1) + da.w);
        z1 = pack2(f_lo(z1) + db.x, f_hi(z1) + db.y);
        w1 = pack2(f_lo(w1) + db.z, f_hi(w1) + db.w);
    }

    stg_cs_32B(&out[(size_t)i0 * EMBED_DIM + j * 8], x0, y0, z0, w0);
    stg_cs_32B(&out[(size_t)i1 * EMBED_DIM + j * 8], x1, y1, z1, w1);
}

extern "C" void kernel_launch(void* const* d_in, const int* in_sizes, int n_in,
                              void* d_out, int out_size) {
    // metadata order: kernel (f32), indices (i32), emb_update (f32), qs (i32)
    const float* table   = (const float*)d_in[0];
    const int*   indices = (const int*)d_in[1];
    const float* upd     = (const float*)d_in[2];
    const int*   qs      = (const int*)d_in[3];
    float* out = (float*)d_out;

    // M0: (1<<20) ints / 8 per thread = 131072 threads = 512 blocks (exact)
    zero_count_kernel<<<512, 256>>>();
    // K2a: N_UPD/2 threads = 512 blocks (exact)
    count_kernel<<<512, 256>>>(indices);
    // K2w: N_UPD threads = 1024 blocks (exact)
    build_worklist_kernel<<<1024, 256>>>(indices);
    // K2b/K2c: fixed grid, grid-stride over 8*g_ndup tasks
    zero_dup_kernel<<<512, 256>>>(indices);
    scatter_dup_kernel<<<512, 256>>>(indices, upd);
    // K3: N_Q*4 threads = 12800 blocks (exact)
    gather_kernel<<<12800, 256>>>(table, qs, upd, out);
}

// round 9
// speedup vs baseline: 1.2123x; 1.2123x over previous
#include <cuda_runtime.h>
#include <cstdint>

// Problem constants (match reference_code)
#define VOC_SIZE 1000000
#define EMBED_DIM 64
#define N_UPD 262144
#define N_Q (4096 * 200)  // 819200 query rows

// Scratch (allocation-free __device__ globals).
// Per-row linked list of updates:
//   g_head[row] = 1 + index of the last update hitting `row` (0 = untouched)
//   g_next[i]   = 1 + index of the previous update hitting the same row
// Both are fully rebuilt every replay (M0 zeros g_head; K2a writes every
// g_next entry), so each graph replay is deterministic up to fp add order
// (same situation as atomic accumulation).
__device__ int g_head[1 << 20];   // 4 MB (padded to power of two)
__device__ int g_next[N_UPD];     // 1 MB

typedef unsigned long long u64;

// 32-byte table load with L2 evict_last (sm_103a: modifier requires
// .v8.b32 / .v4.b64 width). Duplicate queries re-read table rows; bias them
// to stay resident in L2.
__device__ __forceinline__ void ldg_evict_last_32B(const float* p,
                                                   u64& x, u64& y, u64& z, u64& w) {
    asm("ld.global.nc.L2::evict_last.v4.b64 {%0,%1,%2,%3}, [%4];"
        : "=l"(x), "=l"(y), "=l"(z), "=l"(w) : "l"(p));
}

// Streaming store (evict-first): output is written once and never re-read.
__device__ __forceinline__ void stg_cs_32B(float* p, u64 x, u64 y, u64 z, u64 w) {
    asm volatile("st.global.cs.v4.b64 [%0], {%1,%2,%3,%4};"
                 :: "l"(p), "l"(x), "l"(y), "l"(z), "l"(w) : "memory");
}

__device__ __forceinline__ u64 pack2(float lo, float hi) {
    return ((u64)__float_as_uint(hi) << 32) | (u64)__float_as_uint(lo);
}
__device__ __forceinline__ float f_lo(u64 v) { return __uint_as_float((unsigned)v); }
__device__ __forceinline__ float f_hi(u64 v) { return __uint_as_float((unsigned)(v >> 32)); }

// M0: zero the head array (4 MB contiguous). 131072 threads x 32B.
__global__ void zero_head_kernel() {
    int t = blockIdx.x * blockDim.x + threadIdx.x;
    u64 z = 0ULL;
    asm volatile("st.global.v4.b64 [%0], {%1,%1,%1,%1};"
                 :: "l"(&g_head[t * 8]), "l"(z) : "memory");
}

// K2a: build per-row linked lists of updates. Two independent updates per
// thread for MLP. atomicExch gives each row a race-free chain regardless of
// arrival order.
__global__ void link_kernel(const int* __restrict__ indices) {
    int t = blockIdx.x * blockDim.x + threadIdx.x;   // 0 .. N_UPD/2-1
    int i1 = t + N_UPD / 2;
    int r0 = indices[t];
    int r1 = indices[i1];
    int o0 = atomicExch(&g_head[r0], t + 1);
    int o1 = atomicExch(&g_head[r1], i1 + 1);
    g_next[t]  = o0;
    g_next[i1] = o1;
}

// K3: gather. out[q] = table[q] + sum over the update chain of row q.
// 8 threads per 256B row, 32B per thread; each thread handles two query rows
// (i, i+N_Q/2) for MLP. All 8 lanes of a row-group walk the same chain (no
// intra-group divergence; g_head/g_next are small and L2-hot). Table reads:
// L2 evict_last. Output: streaming stores.
__global__ void gather_kernel(const float* __restrict__ table,
                              const int* __restrict__ qs,
                              const float* __restrict__ upd,
                              float* __restrict__ out) {
    int t = blockIdx.x * blockDim.x + threadIdx.x;   // 0 .. N_Q*4-1
    int i0 = t >> 3;
    int j  = t & 7;
    int i1 = i0 + (N_Q / 2);

    int r0 = qs[i0];
    int r1 = qs[i1];
    size_t o0 = (size_t)r0 * EMBED_DIM + j * 8;
    size_t o1 = (size_t)r1 * EMBED_DIM + j * 8;

    u64 x0, y0, z0, w0, x1, y1, z1, w1;
    ldg_evict_last_32B(&table[o0], x0, y0, z0, w0);
    ldg_evict_last_32B(&table[o1], x1, y1, z1, w1);
    int p0 = g_head[r0];
    int p1 = g_head[r1];

    if (p0) {
        float4 sa = make_float4(0.f, 0.f, 0.f, 0.f);
        float4 sb = make_float4(0.f, 0.f, 0.f, 0.f);
        do {
            int i = p0 - 1;
            const float4* up = reinterpret_cast<const float4*>(
                &upd[(size_t)i * EMBED_DIM + j * 8]);
            float4 da = __ldg(up);
            float4 db = __ldg(up + 1);
            sa.x += da.x; sa.y += da.y; sa.z += da.z; sa.w += da.w;
            sb.x += db.x; sb.y += db.y; sb.z += db.z; sb.w += db.w;
            p0 = g_next[i];
        } while (p0);
        x0 = pack2(f_lo(x0) + sa.x, f_hi(x0) + sa.y);
        y0 = pack2(f_lo(y0) + sa.z, f_hi(y0) + sa.w);
        z0 = pack2(f_lo(z0) + sb.x, f_hi(z0) + sb.y);
        w0 = pack2(f_lo(w0) + sb.z, f_hi(w0) + sb.w);
    }
    if (p1) {
        float4 sa = make_float4(0.f, 0.f, 0.f, 0.f);
        float4 sb = make_float4(0.f, 0.f, 0.f, 0.f);
        do {
            int i = p1 - 1;
            const float4* up = reinterpret_cast<const float4*>(
                &upd[(size_t)i * EMBED_DIM + j * 8]);
            float4 da = __ldg(up);
            float4 db = __ldg(up + 1);
            sa.x += da.x; sa.y += da.y; sa.z += da.z; sa.w += da.w;
            sb.x += db.x; sb.y += db.y; sb.z += db.z; sb.w += db.w;
            p1 = g_next[i];
        } while (p1);
        x1 = pack2(f_lo(x1) + sa.x, f_hi(x1) + sa.y);
        y1 = pack2(f_lo(y1) + sa.z, f_hi(y1) + sa.w);
        z1 = pack2(f_lo(z1) + sb.x, f_hi(z1) + sb.y);
        w1 = pack2(f_lo(w1) + sb.z, f_hi(w1) + sb.w);
    }

    stg_cs_32B(&out[(size_t)i0 * EMBED_DIM + j * 8], x0, y0, z0, w0);
    stg_cs_32B(&out[(size_t)i1 * EMBED_DIM + j * 8], x1, y1, z1, w1);
}

extern "C" void kernel_launch(void* const* d_in, const int* in_sizes, int n_in,
                              void* d_out, int out_size) {
    // metadata order: kernel (f32), indices (i32), emb_update (f32), qs (i32)
    const float* table   = (const float*)d_in[0];
    const int*   indices = (const int*)d_in[1];
    const float* upd     = (const float*)d_in[2];
    const int*   qs      = (const int*)d_in[3];
    float* out = (float*)d_out;

    // M0: (1<<20) ints / 8 per thread = 131072 threads = 512 blocks (exact)
    zero_head_kernel<<<512, 256>>>();
    // K2a: N_UPD/2 threads = 512 blocks (exact)
    link_kernel<<<512, 256>>>(indices);
    // K3: N_Q*4 threads = 12800 blocks (exact)
    gather_kernel<<<12800, 256>>>(table, qs, upd, out);
}